// round 1
// baseline (speedup 1.0000x reference)
#include <cuda_runtime.h>

// ---------------------------------------------------------------------------
// CarryII: 7x (gather src features -> segment_sum onto dst) with D=32 fp32.
// Each relation: out[d_idx[e], :] += feat[s_idx[e], :], out zero-initialized.
// Warp-per-edge: 32 lanes cover the 32-float (128B = one L2 line) row, so
// both gather and scatter are line-granular. atomicAdd w/ unused return ->
// RED.E.ADD.F32 (fire-and-forget reduction at L2).
// ---------------------------------------------------------------------------

static constexpr int FEAT_D = 32;

__global__ void zero_f4_kernel(float4* __restrict__ out, long long n4) {
    long long i = blockIdx.x * (long long)blockDim.x + threadIdx.x;
    if (i < n4) out[i] = make_float4(0.f, 0.f, 0.f, 0.f);
}

__global__ void scatter_add_kernel(const float* __restrict__ feat,
                                   const int* __restrict__ s_idx,
                                   const int* __restrict__ d_idx,
                                   float* __restrict__ out,
                                   int n_edges) {
    long long gid = blockIdx.x * (long long)blockDim.x + threadIdx.x;
    int edge = (int)(gid >> 5);
    if (edge >= n_edges) return;
    int lane = (int)(gid & 31);

    int s = __ldg(s_idx + edge);   // broadcast within warp (same address)
    int d = __ldg(d_idx + edge);

    float v = __ldg(feat + (long long)s * FEAT_D + lane);  // coalesced 128B
    atomicAdd(out + (long long)d * FEAT_D + lane, v);      // RED.E.ADD.F32
}

static inline void launch_scatter(const float* feat, const int* s, const int* d,
                                  float* out, int n_edges) {
    long long threads = (long long)n_edges * 32;
    int grid = (int)((threads + 255) / 256);
    scatter_add_kernel<<<grid, 256>>>(feat, s, d, out, n_edges);
}

extern "C" void kernel_launch(void* const* d_in, const int* in_sizes, int n_in,
                              void* d_out, int out_size) {
    // Inputs (metadata order):
    // 0: u2 [N2*32 f32]   1: u3 [N3*32 f32]
    // 2: s_b0a 3: d_b0a 4: s_b1a 5: d_b1a           (N3 edges each)
    // 6: s_b0t 7: d_b0t 8: s_b1t 9: d_b1t 10: s_b2t 11: d_b2t  (N4 edges each)
    // 12: s_a0t 13: d_a0t 14: s_a1t 15: d_a1t       (N4 edges each)
    const float* u2 = (const float*)d_in[0];
    const float* u3 = (const float*)d_in[1];

    const int* s_b0a = (const int*)d_in[2];
    const int* d_b0a = (const int*)d_in[3];
    const int* s_b1a = (const int*)d_in[4];
    const int* d_b1a = (const int*)d_in[5];
    const int* s_b0t = (const int*)d_in[6];
    const int* d_b0t = (const int*)d_in[7];
    const int* s_b1t = (const int*)d_in[8];
    const int* d_b1t = (const int*)d_in[9];
    const int* s_b2t = (const int*)d_in[10];
    const int* d_b2t = (const int*)d_in[11];
    const int* s_a0t = (const int*)d_in[12];
    const int* d_a0t = (const int*)d_in[13];
    const int* s_a1t = (const int*)d_in[14];
    const int* d_a1t = (const int*)d_in[15];

    const int N3 = in_sizes[2];   // edges in n2->n3 relations (and rows of out0/out1)
    const int N4 = in_sizes[6];   // edges in *->n4 relations (rows of out2..out6)

    float* out = (float*)d_out;

    // Zero-init all 7 output blocks (harness poisons d_out with 0xAA).
    {
        long long n4 = (long long)out_size / 4;   // out_size % 4 == 0 (D=32)
        int grid = (int)((n4 + 255) / 256);
        zero_f4_kernel<<<grid, 256>>>((float4*)d_out, n4);
    }

    const long long blk3 = (long long)N3 * FEAT_D;
    const long long blk4 = (long long)N4 * FEAT_D;

    float* o = out;
    launch_scatter(u2, s_b0a, d_b0a, o, N3); o += blk3;  // u_left
    launch_scatter(u2, s_b1a, d_b1a, o, N3); o += blk3;  // u_right
    launch_scatter(u2, s_b0t, d_b0t, o, N4); o += blk4;  // u_bond_left
    launch_scatter(u2, s_b1t, d_b1t, o, N4); o += blk4;  // u_bond_center
    launch_scatter(u2, s_b2t, d_b2t, o, N4); o += blk4;  // u_bond_right
    launch_scatter(u3, s_a0t, d_a0t, o, N4); o += blk4;  // u_angle_left
    launch_scatter(u3, s_a1t, d_a1t, o, N4);             // u_angle_right
}

// round 2
// speedup vs baseline: 2.4923x; 2.4923x over previous
#include <cuda_runtime.h>

// ---------------------------------------------------------------------------
// CarryII R2: 7x (gather -> scatter-add) with D=32 fp32.
// R1 post-mortem: scalar RED.E.ADD.F32 issue floor (416M lanes) was binding
// (issue 28.8%, DRAM only 22%). Fix: red.global.v4.f32.add (sm_90+) -> 4x
// fewer RED + LDG instructions. 8 lanes per edge, one float4 per lane.
// ---------------------------------------------------------------------------

static constexpr int FEAT_D = 32;

__global__ void zero_f4_kernel(float4* __restrict__ out, long long n4) {
    long long i = blockIdx.x * (long long)blockDim.x + threadIdx.x;
    if (i < n4) out[i] = make_float4(0.f, 0.f, 0.f, 0.f);
}

__device__ __forceinline__ void red_add_v4(float* addr, float4 v) {
    asm volatile("red.global.v4.f32.add [%0], {%1, %2, %3, %4};"
                 :: "l"(addr), "f"(v.x), "f"(v.y), "f"(v.z), "f"(v.w)
                 : "memory");
}

__global__ void scatter_add_v4_kernel(const float4* __restrict__ feat,
                                      const int* __restrict__ s_idx,
                                      const int* __restrict__ d_idx,
                                      float* __restrict__ out,
                                      int n_edges) {
    long long gid = blockIdx.x * (long long)blockDim.x + threadIdx.x;
    int edge = (int)(gid >> 3);          // 8 lanes per edge
    if (edge >= n_edges) return;
    int sub = (int)(gid & 7);            // which float4 of the row

    int s = __ldg(s_idx + edge);
    int d = __ldg(d_idx + edge);

    // gather: 8 consecutive lanes read 8 consecutive float4 = one 128B line
    float4 v = __ldg(feat + (long long)s * 8 + sub);
    // scatter: one 16B vector reduction per lane, line-granular per edge
    red_add_v4(out + (long long)d * FEAT_D + sub * 4, v);
}

static inline void launch_scatter(const float* feat, const int* s, const int* d,
                                  float* out, int n_edges) {
    long long threads = (long long)n_edges * 8;
    int grid = (int)((threads + 255) / 256);
    scatter_add_v4_kernel<<<grid, 256>>>((const float4*)feat, s, d, out, n_edges);
}

extern "C" void kernel_launch(void* const* d_in, const int* in_sizes, int n_in,
                              void* d_out, int out_size) {
    const float* u2 = (const float*)d_in[0];
    const float* u3 = (const float*)d_in[1];

    const int* s_b0a = (const int*)d_in[2];
    const int* d_b0a = (const int*)d_in[3];
    const int* s_b1a = (const int*)d_in[4];
    const int* d_b1a = (const int*)d_in[5];
    const int* s_b0t = (const int*)d_in[6];
    const int* d_b0t = (const int*)d_in[7];
    const int* s_b1t = (const int*)d_in[8];
    const int* d_b1t = (const int*)d_in[9];
    const int* s_b2t = (const int*)d_in[10];
    const int* d_b2t = (const int*)d_in[11];
    const int* s_a0t = (const int*)d_in[12];
    const int* d_a0t = (const int*)d_in[13];
    const int* s_a1t = (const int*)d_in[14];
    const int* d_a1t = (const int*)d_in[15];

    const int N3 = in_sizes[2];
    const int N4 = in_sizes[6];

    float* out = (float*)d_out;

    // Zero-init all 7 output blocks (harness poisons d_out with 0xAA).
    {
        long long n4 = (long long)out_size / 4;
        int grid = (int)((n4 + 255) / 256);
        zero_f4_kernel<<<grid, 256>>>((float4*)d_out, n4);
    }

    const long long blk3 = (long long)N3 * FEAT_D;
    const long long blk4 = (long long)N4 * FEAT_D;

    float* o = out;
    launch_scatter(u2, s_b0a, d_b0a, o, N3); o += blk3;  // u_left
    launch_scatter(u2, s_b1a, d_b1a, o, N3); o += blk3;  // u_right
    launch_scatter(u2, s_b0t, d_b0t, o, N4); o += blk4;  // u_bond_left
    launch_scatter(u2, s_b1t, d_b1t, o, N4); o += blk4;  // u_bond_center
    launch_scatter(u2, s_b2t, d_b2t, o, N4); o += blk4;  // u_bond_right
    launch_scatter(u3, s_a0t, d_a0t, o, N4); o += blk4;  // u_angle_left
    launch_scatter(u3, s_a1t, d_a1t, o, N4);             // u_angle_right
}